// round 11
// baseline (speedup 1.0000x reference)
#include <cuda_runtime.h>
#include <cstdint>

// ---------------- configuration ----------------
#define HB_BITS   16
#define HB        (1u << HB_BITS)     // 65536 coarse bins (top 16 bits of mono key)
#define LOWB      16
#define LOWN      (1u << LOWB)        // 65536 fine bins (low 16 bits)
#define NPART     148                 // one coarse-hist block per SM
#define MAX_SLOTS 32
#define NSEG      16
#define SEG_BINS  (LOWN / NSEG)       // 4096 bins per scan segment
#define QL_BITS   13
#define QLN       (1u << QL_BITS)     // 8192-entry quant LUT (top 13 bits)

// ---------------- static scratch ----------------
__device__ __align__(16) unsigned g_part1[(size_t)NPART * HB];       // 38.8 MB, fully overwritten each run
__device__ __align__(16) unsigned g_hist16[HB];                      // 256 KB, fully overwritten
__device__ __align__(16) unsigned g_hist2[(size_t)MAX_SLOTS * LOWN]; // 8 MB, zeroed by k_zero2
__device__ __align__(16) unsigned g_part2[MAX_SLOTS][NSEG];
__device__ __align__(16) unsigned char g_lut16[HB];                  // coarse bin -> slot+1 (rebuilt each run)
__device__ __align__(16) unsigned char g_qlut[QLN];                  // quant LUT (rebuilt each run)
__device__ int      g_tbin[32];
__device__ unsigned g_trr[32];
__device__ int      g_tslot[32];
__device__ int      g_nslots;
__device__ float    g_tval[32];
__device__ float    g_cut[16];
__device__ float4   g_q[16];          // x=mn, y=step, z=1/step

// order-preserving float32 <-> uint32 key
__device__ __forceinline__ unsigned mono_key(float f) {
    unsigned b = __float_as_uint(f);
    unsigned m = (unsigned)(((int)b) >> 31) | 0x80000000u;
    return b ^ m;
}
__device__ __forceinline__ float unmono_key(unsigned k) {
    unsigned b = (k & 0x80000000u) ? (k & 0x7FFFFFFFu) : ~k;
    return __uint_as_float(b);
}

// ---------------- pass 1: 16-bit coarse histogram, packed u16 counters ----------------
__global__ void __launch_bounds__(1024) k_hist1(const float4* __restrict__ x, int n4) {
    extern __shared__ unsigned sh[];              // HB/2 = 32768 words (128 KB)
    for (int i = threadIdx.x; i < (int)(HB / 2); i += 1024) sh[i] = 0u;
    __syncthreads();
    int T = gridDim.x * blockDim.x;
    int g = blockIdx.x * blockDim.x + threadIdx.x;
    for (int i = g; i < n4; i += 2 * T) {
        float4 a = x[i];
        bool hb = (i + T) < n4;
        float4 b = hb ? x[i + T] : a;
        unsigned k0 = mono_key(a.x) >> LOWB, k1 = mono_key(a.y) >> LOWB;
        unsigned k2 = mono_key(a.z) >> LOWB, k3 = mono_key(a.w) >> LOWB;
        atomicAdd(&sh[k0 >> 1], 1u << ((k0 & 1u) << 4));
        atomicAdd(&sh[k1 >> 1], 1u << ((k1 & 1u) << 4));
        atomicAdd(&sh[k2 >> 1], 1u << ((k2 & 1u) << 4));
        atomicAdd(&sh[k3 >> 1], 1u << ((k3 & 1u) << 4));
        if (hb) {
            unsigned j0 = mono_key(b.x) >> LOWB, j1 = mono_key(b.y) >> LOWB;
            unsigned j2 = mono_key(b.z) >> LOWB, j3 = mono_key(b.w) >> LOWB;
            atomicAdd(&sh[j0 >> 1], 1u << ((j0 & 1u) << 4));
            atomicAdd(&sh[j1 >> 1], 1u << ((j1 & 1u) << 4));
            atomicAdd(&sh[j2 >> 1], 1u << ((j2 & 1u) << 4));
            atomicAdd(&sh[j3 >> 1], 1u << ((j3 & 1u) << 4));
        }
    }
    __syncthreads();
    uint2* dst = (uint2*)(g_part1 + (size_t)blockIdx.x * HB);
    for (int i = threadIdx.x; i < (int)(HB / 2); i += 1024) {
        unsigned w = sh[i];
        dst[i] = make_uint2(w & 0xFFFFu, w >> 16);
    }
}

// ---------------- reduce partial histograms ----------------
__global__ void __launch_bounds__(1024) k_reduce() {
    unsigned bin = blockIdx.x * 1024u + threadIdx.x;
    unsigned s = 0;
#pragma unroll 4
    for (int k = 0; k < NPART; k++) s += g_part1[(size_t)k * HB + bin];
    g_hist16[bin] = s;
}

// ---------------- scan coarse histogram, locate target bins, build slot LUT ----------------
__global__ void __launch_bounds__(1024) k_scan1(unsigned n) {
    __shared__ unsigned pre[1024];
    __shared__ unsigned wsum[32];
    __shared__ int      sbin[32];
    __shared__ unsigned srr[32];
    __shared__ int      sslot[32];

    int t = threadIdx.x, lane = t & 31, w = t >> 5;
    unsigned s = 0;
    for (int k = 0; k < 64; k++) s += g_hist16[t * 64 + k];  // group sum (64 bins/thread)

    unsigned inc = s;
#pragma unroll
    for (int o = 1; o < 32; o <<= 1) {
        unsigned u = __shfl_up_sync(0xFFFFFFFFu, inc, o);
        if (lane >= o) inc += u;
    }
    if (lane == 31) wsum[w] = inc;
    __syncthreads();
    if (t < 32) {
        unsigned v = wsum[t], ss = v;
#pragma unroll
        for (int o = 1; o < 32; o <<= 1) {
            unsigned u = __shfl_up_sync(0xFFFFFFFFu, ss, o);
            if (t >= o) ss += u;
        }
        wsum[t] = ss - v;
    }
    __syncthreads();
    pre[t] = inc + wsum[w];          // inclusive prefix of 1024 group sums
    __syncthreads();

    if (t < 32) {
        unsigned S = n >> 4;
        unsigned r;
        if (t == 0)       r = 0u;
        else if (t == 31) r = n - 1u;
        else {
            unsigned c = (unsigned)(t + 1) >> 1;
            r = c * S - ((t & 1) ? 1u : 0u);
        }
        int lo = 0, hi = 1023;
        while (lo < hi) { int mid = (lo + hi) >> 1; if (pre[mid] > r) hi = mid; else lo = mid + 1; }
        unsigned run = lo ? pre[lo - 1] : 0u;
        int bin = -1;
        for (int k = 0; k < 64; k++) {
            unsigned c = g_hist16[lo * 64 + k];
            if (r < run + c) { bin = lo * 64 + k; srr[t] = r - run; break; }
            run += c;
        }
        sbin[t] = bin;
    }
    __syncthreads();

    for (int i = t; i < (int)HB; i += 1024) g_lut16[i] = 0;  // zero slot LUT
    if (t == 0) {
        int ns = 0;
        for (int i = 0; i < 32; i++) {
            int sl = -1;
            for (int j = 0; j < i; j++) if (sbin[j] == sbin[i]) { sl = sslot[j]; break; }
            if (sl < 0) sl = ns++;
            sslot[i] = sl;
        }
        g_nslots = ns;
    }
    __syncthreads();
    if (t == 0) for (int i = 0; i < 32; i++) g_lut16[sbin[i]] = (unsigned char)(sslot[i] + 1);
    if (t < 32) { g_tbin[t] = sbin[t]; g_trr[t] = srr[t]; g_tslot[t] = sslot[t]; }
}

// ---------------- pass 2: fine histogram (low 16 bits) for cut bins ----------------
__global__ void __launch_bounds__(512) k_hist2(const float4* __restrict__ x, int n4) {
    extern __shared__ unsigned char lut[];   // 64 KB
    {
        const uint4* src = (const uint4*)g_lut16;
        uint4* dst = (uint4*)lut;
        for (int i = threadIdx.x; i < (int)(HB / 16); i += 512) dst[i] = src[i];
    }
    __syncthreads();
    int T = gridDim.x * blockDim.x;
    int g = blockIdx.x * blockDim.x + threadIdx.x;
    for (int i = g; i < n4; i += 2 * T) {
        float4 a = x[i];
        bool hb = (i + T) < n4;
        float4 b = hb ? x[i + T] : a;
        unsigned k[8];
        k[0] = mono_key(a.x); k[1] = mono_key(a.y); k[2] = mono_key(a.z); k[3] = mono_key(a.w);
        k[4] = mono_key(b.x); k[5] = mono_key(b.y); k[6] = mono_key(b.z); k[7] = mono_key(b.w);
        int nv = hb ? 8 : 4;
#pragma unroll
        for (int j = 0; j < 8; j++) {
            if (j < nv) {
                unsigned char sl = lut[k[j] >> LOWB];
                if (sl) atomicAdd(&g_hist2[(size_t)(sl - 1) * LOWN + (k[j] & (LOWN - 1u))], 1u);
            }
        }
    }
}

// ---------------- scan2a: per-segment partial sums ----------------
__global__ void __launch_bounds__(256) k_scan2a() {
    int slot = blockIdx.x / NSEG;
    if (slot >= g_nslots) return;
    int seg = blockIdx.x % NSEG;
    const uint4* h = (const uint4*)(g_hist2 + (size_t)slot * LOWN + (size_t)seg * SEG_BINS);
    int t = threadIdx.x;
    unsigned s = 0;
#pragma unroll
    for (int i = 0; i < 4; i++) {               // 16 bins per thread
        uint4 u = h[t * 4 + i];
        s += u.x + u.y + u.z + u.w;
    }
#pragma unroll
    for (int o = 16; o; o >>= 1) s += __shfl_down_sync(0xFFFFFFFFu, s, o);
    __shared__ unsigned ws[8];
    if ((t & 31) == 0) ws[t >> 5] = s;
    __syncthreads();
    if (t < 8) {
        unsigned v = ws[t];
#pragma unroll
        for (int o = 4; o; o >>= 1) v += __shfl_down_sync(0xFFu, v, o, 8);
        if (t == 0) g_part2[slot][seg] = v;
    }
}

// ---------------- scan2b: exact order statistic per target ----------------
__global__ void __launch_bounds__(128) k_scan2b() {
    int t = blockIdx.x;
    int slot = g_tslot[t];
    unsigned rr = g_trr[t];
    unsigned bin = (unsigned)g_tbin[t];
    int tid = threadIdx.x;

    __shared__ int s_seg;
    __shared__ unsigned s_rr2;
    __shared__ unsigned s[128];

    if (tid == 0) {
        unsigned run = 0; int seg = -1;
        for (int k = 0; k < NSEG; k++) {
            unsigned c = g_part2[slot][k];
            if (seg < 0 && rr < run + c) { seg = k; s_rr2 = rr - run; }
            run += c;
        }
        s_seg = seg;
    }
    __syncthreads();
    int seg = s_seg;
    unsigned rr2 = s_rr2;

    const uint4* h = (const uint4*)(g_hist2 + (size_t)slot * LOWN + (size_t)seg * SEG_BINS);
    uint4 u[8];
    unsigned sum = 0;
#pragma unroll
    for (int i = 0; i < 8; i++) {               // 32 bins per thread
        u[i] = h[tid * 8 + i];
        sum += u[i].x + u[i].y + u[i].z + u[i].w;
    }
    s[tid] = sum; __syncthreads();
    for (int o = 1; o < 128; o <<= 1) {
        unsigned v = (tid >= o) ? s[tid - o] : 0u;
        __syncthreads();
        s[tid] += v;
        __syncthreads();
    }
    unsigned incl2 = s[tid], excl2 = incl2 - sum;
    if (rr2 >= excl2 && rr2 < incl2) {
        unsigned run = excl2, low = 0;
        bool found = false;
        for (int i = 0; i < 8 && !found; i++) {
            unsigned vv[4] = { u[i].x, u[i].y, u[i].z, u[i].w };
            for (int j = 0; j < 4; j++) {
                if (!found) {
                    if (rr2 < run + vv[j]) { low = (unsigned)(tid * 32 + i * 4 + j); found = true; }
                    else run += vv[j];
                }
            }
        }
        unsigned key = (bin << LOWB) | ((unsigned)seg * SEG_BINS + low);
        g_tval[t] = unmono_key(key);
    }
}

// ---------------- zero used fine-hist slots for replay ----------------
__global__ void __launch_bounds__(256) k_zero2() {
    unsigned total4 = (unsigned)g_nslots * (LOWN / 4u);
    uint4* p = (uint4*)g_hist2;
    uint4 z = make_uint4(0u, 0u, 0u, 0u);
    unsigned stride = gridDim.x * blockDim.x;
    for (unsigned i = blockIdx.x * blockDim.x + threadIdx.x; i < total4; i += stride) p[i] = z;
}

// ---------------- per-chunk params ----------------
__global__ void k_params() {
    int c = threadIdx.x;
    if (c < 16) {
        float mn = (c == 0)  ? g_tval[0]  : g_tval[2 * c];
        float mx = (c == 15) ? g_tval[31] : g_tval[2 * c + 1];
        float step = __fdiv_rn(__fsub_rn(mx, mn), 15.0f);
        float inv  = (step == 0.0f) ? 0.0f : __fdiv_rn(1.0f, step);
        g_q[c] = make_float4(mn, step, inv, 0.0f);
        g_cut[c] = (c == 0) ? __int_as_float(0xFF800000) : mn;
    }
}

// ---------------- build 13-bit quant LUT: bin -> (base chunk, #ambiguous cuts) ----------------
__global__ void __launch_bounds__(1024) k_blut() {
    __shared__ unsigned kc[16];
    if (threadIdx.x >= 1 && threadIdx.x < 16) kc[threadIdx.x] = mono_key(g_cut[threadIdx.x]);
    __syncthreads();
    unsigned bin = blockIdx.x * 1024u + threadIdx.x;
    unsigned long long base = (unsigned long long)bin << (32 - QL_BITS);
    unsigned long long nxt  = base + (1ull << (32 - QL_BITS));
    int lo = 0, amb = 0;
#pragma unroll
    for (int j = 1; j < 16; j++) {
        unsigned long long k = kc[j];
        lo  += (k <= base);
        amb += (k > base && k < nxt);
    }
    g_qlut[bin] = (unsigned char)(lo | (amb << 4));
}

// ---------------- final quantize pass ----------------
__device__ __forceinline__ float qone(float v, float mn_r, float step_r, float inv_r,
                                      float cut_r, const unsigned char* lut) {
    unsigned e = lut[mono_key(v) >> (32 - QL_BITS)];
    int c = e & 15, amb = e >> 4;
    while (__ballot_sync(0xFFFFFFFFu, amb > 0)) {           // warp-convergent, usually 0-1 iters
        float cc = __shfl_sync(0xFFFFFFFFu, cut_r, (c + 1) & 15);
        if (amb > 0) { c += (v >= cc) ? 1 : 0; amb--; }
    }
    float mn = __shfl_sync(0xFFFFFFFFu, mn_r,  c);
    float st = __shfl_sync(0xFFFFFFFFu, step_r, c);
    float iv = __shfl_sync(0xFFFFFFFFu, inv_r,  c);
    float q = rintf((v - mn) * iv) * st + mn;
    return (st == 0.0f) ? v : q;
}

__global__ void __launch_bounds__(256) k_quant(const float4* __restrict__ x,
                                               float4* __restrict__ o, int n4) {
    __shared__ unsigned char lut[QLN];
    {
        const uint4* src = (const uint4*)g_qlut;
        uint4* dst = (uint4*)lut;
        for (int i = threadIdx.x; i < (int)(QLN / 16); i += 256) dst[i] = src[i];
    }
    int lane = threadIdx.x & 31;
    float mn_r = 0.f, step_r = 0.f, inv_r = 0.f, cut_r = 0.f;
    if (lane < 16) {
        float4 q = g_q[lane];
        mn_r = q.x; step_r = q.y; inv_r = q.z;
        cut_r = g_cut[lane];
    }
    __syncthreads();
    int T = gridDim.x * blockDim.x;
    int g = blockIdx.x * blockDim.x + threadIdx.x;
    for (int i = g; i < n4; i += 2 * T) {        // bounds are warp-uniform: n4, T multiples of 32
        float4 a = x[i];
        bool hb = (i + T) < n4;
        float4 b = hb ? x[i + T] : a;
        float4 ra, rb;
        ra.x = qone(a.x, mn_r, step_r, inv_r, cut_r, lut);
        ra.y = qone(a.y, mn_r, step_r, inv_r, cut_r, lut);
        ra.z = qone(a.z, mn_r, step_r, inv_r, cut_r, lut);
        ra.w = qone(a.w, mn_r, step_r, inv_r, cut_r, lut);
        rb.x = qone(b.x, mn_r, step_r, inv_r, cut_r, lut);
        rb.y = qone(b.y, mn_r, step_r, inv_r, cut_r, lut);
        rb.z = qone(b.z, mn_r, step_r, inv_r, cut_r, lut);
        rb.w = qone(b.w, mn_r, step_r, inv_r, cut_r, lut);
        o[i] = ra;
        if (hb) o[i + T] = rb;
    }
}

// ---------------- launcher ----------------
extern "C" void kernel_launch(void* const* d_in, const int* in_sizes, int n_in,
                              void* d_out, int out_size) {
    const float4* x = (const float4*)d_in[0];
    float4* out = (float4*)d_out;
    int n = in_sizes[0];
    int n4 = n / 4;

    cudaFuncSetAttribute(k_hist1, cudaFuncAttributeMaxDynamicSharedMemorySize, 131072);
    cudaFuncSetAttribute(k_hist2, cudaFuncAttributeMaxDynamicSharedMemorySize, 65536);

    k_hist1  <<< NPART, 1024, 131072 >>> (x, n4);   // 16-bit coarse histogram (packed u16, per-SM)
    k_reduce <<< HB / 1024, 1024 >>> ();            // sum partials -> g_hist16
    k_scan1  <<< 1, 1024 >>> ((unsigned)n);         // locate cut bins, slots, slot LUT
    k_hist2  <<< 888, 512, 65536 >>> (x, n4);       // fine histogram (low 16 bits), L2-resident
    k_scan2a <<< MAX_SLOTS * NSEG, 256 >>> ();      // per-segment partial sums
    k_scan2b <<< 32, 128 >>> ();                    // exact order statistics
    k_zero2  <<< 128, 256 >>> ();                   // re-zero used fine-hist slots (8 MB max)
    k_params <<< 1, 32 >>> ();                      // mn/step/inv + cuts
    k_blut   <<< QLN / 1024, 1024 >>> ();           // 13-bit bin -> chunk LUT
    k_quant  <<< 1184, 256 >>> (x, out, n4);        // elementwise quantize (shuffle params, no div)
}

// round 12
// speedup vs baseline: 1.0265x; 1.0265x over previous
#include <cuda_runtime.h>
#include <cstdint>

// ---------------- configuration ----------------
#define HB_BITS   16
#define HB        (1u << HB_BITS)     // 65536 coarse bins (top 16 raw bits)
#define LOWB      16
#define LOWN      (1u << LOWB)        // 65536 fine bins (low 16 mono bits)
#define NPART     148                 // one coarse-hist block per SM
#define MAX_SLOTS 32
#define NSEG      16
#define SEG_BINS  (LOWN / NSEG)       // 4096 bins per scan segment
#define QL_BITS   13
#define QLN       (1u << QL_BITS)     // 8192-entry quant LUT (top 13 raw bits)

// ---------------- static scratch ----------------
__device__ __align__(16) unsigned g_part1[(size_t)NPART * (HB / 2)];   // 19.4 MB packed u16, overwritten each run
__device__ __align__(16) unsigned g_hist16[HB];                        // mono-indexed, overwritten by k_reduce
__device__ __align__(16) unsigned g_hist2[(size_t)MAX_SLOTS * LOWN];   // 8 MB, zeroed by k_zero2
__device__ __align__(16) unsigned g_part2[MAX_SLOTS][NSEG];
__device__ __align__(16) unsigned char g_lut16[HB];                    // RAW coarse bin -> slot+1 (rebuilt each run)
__device__ __align__(16) unsigned char g_qlut[QLN];                    // RAW 13-bit bin -> base | amb<<4 (rebuilt)
__device__ int      g_tbin[32];       // mono coarse bins of targets
__device__ unsigned g_trr[32];
__device__ int      g_tslot[32];
__device__ int      g_nslots;
__device__ float    g_tval[32];
__device__ float    g_cutv[16];
__device__ float4   g_q[16];          // x=mn, y=step, z=inv, w=mn*inv

// order-preserving maps
__device__ __forceinline__ unsigned mono_bits(unsigned b) {
    return b ^ ((unsigned)(((int)b) >> 31) | 0x80000000u);
}
__device__ __forceinline__ unsigned mono_key(float f) { return mono_bits(__float_as_uint(f)); }
__device__ __forceinline__ float unmono_key(unsigned k) {
    unsigned b = (k & 0x80000000u) ? (k & 0x7FFFFFFFu) : ~k;
    return __uint_as_float(b);
}
// 16-bit bin permutations between raw-bit order and mono (value) order
__device__ __forceinline__ unsigned raw2mono16(unsigned r) { return (r & 0x8000u) ? (r ^ 0xFFFFu) : (r ^ 0x8000u); }
__device__ __forceinline__ unsigned mono2raw16(unsigned m) { return (m & 0x8000u) ? (m ^ 0x8000u) : (m ^ 0xFFFFu); }

// ---------------- pass 1: raw 16-bit coarse histogram, packed u16 counters ----------------
__global__ void __launch_bounds__(1024) k_hist1(const float4* __restrict__ x, int n4) {
    extern __shared__ unsigned sh[];              // HB/2 = 32768 words (128 KB)
    for (int i = threadIdx.x; i < (int)(HB / 2); i += 1024) sh[i] = 0u;
    __syncthreads();
    int T = gridDim.x * blockDim.x;
    int g = blockIdx.x * blockDim.x + threadIdx.x;
    for (int i = g; i < n4; i += 2 * T) {
        float4 a = __ldcs(&x[i]);
        bool hb = (i + T) < n4;
        float4 b = hb ? __ldcs(&x[i + T]) : a;
        unsigned k0 = __float_as_uint(a.x) >> 16, k1 = __float_as_uint(a.y) >> 16;
        unsigned k2 = __float_as_uint(a.z) >> 16, k3 = __float_as_uint(a.w) >> 16;
        atomicAdd(&sh[k0 >> 1], 1u << ((k0 & 1u) << 4));
        atomicAdd(&sh[k1 >> 1], 1u << ((k1 & 1u) << 4));
        atomicAdd(&sh[k2 >> 1], 1u << ((k2 & 1u) << 4));
        atomicAdd(&sh[k3 >> 1], 1u << ((k3 & 1u) << 4));
        if (hb) {
            unsigned j0 = __float_as_uint(b.x) >> 16, j1 = __float_as_uint(b.y) >> 16;
            unsigned j2 = __float_as_uint(b.z) >> 16, j3 = __float_as_uint(b.w) >> 16;
            atomicAdd(&sh[j0 >> 1], 1u << ((j0 & 1u) << 4));
            atomicAdd(&sh[j1 >> 1], 1u << ((j1 & 1u) << 4));
            atomicAdd(&sh[j2 >> 1], 1u << ((j2 & 1u) << 4));
            atomicAdd(&sh[j3 >> 1], 1u << ((j3 & 1u) << 4));
        }
    }
    __syncthreads();
    unsigned* dst = g_part1 + (size_t)blockIdx.x * (HB / 2);
    for (int i = threadIdx.x; i < (int)(HB / 2); i += 1024) dst[i] = sh[i];   // packed
}

// ---------------- reduce packed partials -> mono-ordered g_hist16 ----------------
__global__ void __launch_bounds__(1024) k_reduce() {
    unsigned w = blockIdx.x * 1024u + threadIdx.x;     // packed word index (raw bins 2w, 2w+1)
    unsigned lo = 0, hi = 0;
#pragma unroll 8
    for (int k = 0; k < NPART; k++) {
        unsigned v = g_part1[(size_t)k * (HB / 2) + w];
        lo += v & 0xFFFFu;
        hi += v >> 16;
    }
    g_hist16[raw2mono16(2u * w)]      = lo;
    g_hist16[raw2mono16(2u * w + 1u)] = hi;
}

// ---------------- scan coarse histogram (mono order), locate target bins ----------------
__global__ void __launch_bounds__(1024) k_scan1(unsigned n) {
    __shared__ unsigned pre[1024];
    __shared__ unsigned wsum[32];
    __shared__ int      sbin[32];
    __shared__ unsigned srr[32];
    __shared__ int      sslot[32];

    int t = threadIdx.x, lane = t & 31, w = t >> 5;
    unsigned s = 0;
    for (int k = 0; k < 64; k++) s += g_hist16[t * 64 + k];  // group sum (64 mono bins/thread)

    unsigned inc = s;
#pragma unroll
    for (int o = 1; o < 32; o <<= 1) {
        unsigned u = __shfl_up_sync(0xFFFFFFFFu, inc, o);
        if (lane >= o) inc += u;
    }
    if (lane == 31) wsum[w] = inc;
    __syncthreads();
    if (t < 32) {
        unsigned v = wsum[t], ss = v;
#pragma unroll
        for (int o = 1; o < 32; o <<= 1) {
            unsigned u = __shfl_up_sync(0xFFFFFFFFu, ss, o);
            if (t >= o) ss += u;
        }
        wsum[t] = ss - v;
    }
    __syncthreads();
    pre[t] = inc + wsum[w];          // inclusive prefix of 1024 group sums
    __syncthreads();

    if (t < 32) {
        unsigned S = n >> 4;
        unsigned r;
        if (t == 0)       r = 0u;
        else if (t == 31) r = n - 1u;
        else {
            unsigned c = (unsigned)(t + 1) >> 1;
            r = c * S - ((t & 1) ? 1u : 0u);
        }
        int lo = 0, hi = 1023;
        while (lo < hi) { int mid = (lo + hi) >> 1; if (pre[mid] > r) hi = mid; else lo = mid + 1; }
        unsigned run = lo ? pre[lo - 1] : 0u;
        int bin = -1;
        for (int k = 0; k < 64; k++) {
            unsigned c = g_hist16[lo * 64 + k];
            if (r < run + c) { bin = lo * 64 + k; srr[t] = r - run; break; }
            run += c;
        }
        sbin[t] = bin;
    }
    __syncthreads();

    for (int i = t; i < (int)HB; i += 1024) g_lut16[i] = 0;  // zero slot LUT (raw-indexed)
    if (t == 0) {
        int ns = 0;
        for (int i = 0; i < 32; i++) {
            int sl = -1;
            for (int j = 0; j < i; j++) if (sbin[j] == sbin[i]) { sl = sslot[j]; break; }
            if (sl < 0) sl = ns++;
            sslot[i] = sl;
        }
        g_nslots = ns;
    }
    __syncthreads();
    if (t == 0)
        for (int i = 0; i < 32; i++)
            g_lut16[mono2raw16((unsigned)sbin[i])] = (unsigned char)(sslot[i] + 1);
    if (t < 32) { g_tbin[t] = sbin[t]; g_trr[t] = srr[t]; g_tslot[t] = sslot[t]; }
}

// ---------------- pass 2: fine histogram (low 16 mono bits) for cut bins ----------------
__global__ void __launch_bounds__(512) k_hist2(const float4* __restrict__ x, int n4) {
    extern __shared__ unsigned char lut[];   // 64 KB, raw-indexed
    {
        const uint4* src = (const uint4*)g_lut16;
        uint4* dst = (uint4*)lut;
        for (int i = threadIdx.x; i < (int)(HB / 16); i += 512) dst[i] = src[i];
    }
    __syncthreads();
    int T = gridDim.x * blockDim.x;
    int g = blockIdx.x * blockDim.x + threadIdx.x;
    for (int i = g; i < n4; i += 2 * T) {
        float4 a = __ldcs(&x[i]);
        bool hb = (i + T) < n4;
        float4 b = hb ? __ldcs(&x[i + T]) : a;
        float vv[8] = { a.x, a.y, a.z, a.w, b.x, b.y, b.z, b.w };
        int nv = hb ? 8 : 4;
#pragma unroll
        for (int j = 0; j < 8; j++) {
            if (j < nv) {
                unsigned char sl = lut[__float_as_uint(vv[j]) >> 16];
                if (sl) {
                    unsigned m = mono_key(vv[j]);
                    atomicAdd(&g_hist2[(size_t)(sl - 1) * LOWN + (m & 0xFFFFu)], 1u);
                }
            }
        }
    }
}

// ---------------- scan2a: per-segment partial sums ----------------
__global__ void __launch_bounds__(256) k_scan2a() {
    int slot = blockIdx.x / NSEG;
    if (slot >= g_nslots) return;
    int seg = blockIdx.x % NSEG;
    const uint4* h = (const uint4*)(g_hist2 + (size_t)slot * LOWN + (size_t)seg * SEG_BINS);
    int t = threadIdx.x;
    unsigned s = 0;
#pragma unroll
    for (int i = 0; i < 4; i++) {               // 16 bins per thread
        uint4 u = h[t * 4 + i];
        s += u.x + u.y + u.z + u.w;
    }
#pragma unroll
    for (int o = 16; o; o >>= 1) s += __shfl_down_sync(0xFFFFFFFFu, s, o);
    __shared__ unsigned ws[8];
    if ((t & 31) == 0) ws[t >> 5] = s;
    __syncthreads();
    if (t < 8) {
        unsigned v = ws[t];
#pragma unroll
        for (int o = 4; o; o >>= 1) v += __shfl_down_sync(0xFFu, v, o, 8);
        if (t == 0) g_part2[slot][seg] = v;
    }
}

// ---------------- scan2b: exact order statistic per target ----------------
__global__ void __launch_bounds__(128) k_scan2b() {
    int t = blockIdx.x;
    int slot = g_tslot[t];
    unsigned rr = g_trr[t];
    unsigned bin = (unsigned)g_tbin[t];
    int tid = threadIdx.x;

    __shared__ int s_seg;
    __shared__ unsigned s_rr2;
    __shared__ unsigned s[128];

    if (tid == 0) {
        unsigned run = 0; int seg = -1;
        for (int k = 0; k < NSEG; k++) {
            unsigned c = g_part2[slot][k];
            if (seg < 0 && rr < run + c) { seg = k; s_rr2 = rr - run; }
            run += c;
        }
        s_seg = seg;
    }
    __syncthreads();
    int seg = s_seg;
    unsigned rr2 = s_rr2;

    const uint4* h = (const uint4*)(g_hist2 + (size_t)slot * LOWN + (size_t)seg * SEG_BINS);
    uint4 u[8];
    unsigned sum = 0;
#pragma unroll
    for (int i = 0; i < 8; i++) {               // 32 bins per thread
        u[i] = h[tid * 8 + i];
        sum += u[i].x + u[i].y + u[i].z + u[i].w;
    }
    s[tid] = sum; __syncthreads();
    for (int o = 1; o < 128; o <<= 1) {
        unsigned v = (tid >= o) ? s[tid - o] : 0u;
        __syncthreads();
        s[tid] += v;
        __syncthreads();
    }
    unsigned incl2 = s[tid], excl2 = incl2 - sum;
    if (rr2 >= excl2 && rr2 < incl2) {
        unsigned run = excl2, low = 0;
        bool found = false;
        for (int i = 0; i < 8 && !found; i++) {
            unsigned vv[4] = { u[i].x, u[i].y, u[i].z, u[i].w };
            for (int j = 0; j < 4; j++) {
                if (!found) {
                    if (rr2 < run + vv[j]) { low = (unsigned)(tid * 32 + i * 4 + j); found = true; }
                    else run += vv[j];
                }
            }
        }
        unsigned key = (bin << LOWB) | ((unsigned)seg * SEG_BINS + low);
        g_tval[t] = unmono_key(key);
    }
}

// ---------------- zero used fine-hist slots for replay ----------------
__global__ void __launch_bounds__(256) k_zero2() {
    unsigned total4 = (unsigned)g_nslots * (LOWN / 4u);
    uint4* p = (uint4*)g_hist2;
    uint4 z = make_uint4(0u, 0u, 0u, 0u);
    unsigned stride = gridDim.x * blockDim.x;
    for (unsigned i = blockIdx.x * blockDim.x + threadIdx.x; i < total4; i += stride) p[i] = z;
}

// ---------------- per-chunk params ----------------
__global__ void k_params() {
    int c = threadIdx.x;
    if (c < 16) {
        float mn = (c == 0)  ? g_tval[0]  : g_tval[2 * c];
        float mx = (c == 15) ? g_tval[31] : g_tval[2 * c + 1];
        float step = __fdiv_rn(__fsub_rn(mx, mn), 15.0f);
        float inv  = (step == 0.0f) ? 0.0f : __fdiv_rn(1.0f, step);
        g_q[c] = make_float4(mn, step, inv, __fmul_rn(mn, inv));
        g_cutv[c] = (c == 0) ? __int_as_float(0xFF800000) : mn;
    }
}

// ---------------- build 13-bit RAW-bin quant LUT: base chunk | #ambiguous<<4 ----------------
__global__ void __launch_bounds__(1024) k_blut() {
    __shared__ unsigned kc[16];
    if (threadIdx.x >= 1 && threadIdx.x < 16) kc[threadIdx.x] = mono_key(g_cutv[threadIdx.x]);
    __syncthreads();
    unsigned r = blockIdx.x * 1024u + threadIdx.x;
    unsigned m0 = mono_bits(r << (32 - QL_BITS));
    unsigned m1 = mono_bits((r << (32 - QL_BITS)) | ((1u << (32 - QL_BITS)) - 1u));
    unsigned mlo = min(m0, m1), mhi = max(m0, m1);
    int base = 0, amb = 0;
#pragma unroll
    for (int j = 1; j < 16; j++) {
        unsigned k = kc[j];
        base += (k <= mlo);
        amb  += (k > mlo && k <= mhi);
    }
    g_qlut[r] = (unsigned char)(base | (amb << 4));
}

// ---------------- final quantize pass ----------------
__device__ __forceinline__ float qone(float v, const unsigned char* lut,
                                      const float4* sq, const float* scut) {
    unsigned e = lut[__float_as_uint(v) >> (32 - QL_BITS)];
    int c = e & 15;
    int amb = e >> 4;
    if (amb) {                                   // rare: cut(s) inside this bin
        int b = c;
        for (int t = 1; t <= amb; t++) c += (v >= scut[b + t]) ? 1 : 0;
    }
    float4 p = sq[c];                            // {mn, step, inv, mn*inv}
    float tq = fmaf(v, p.z, -p.w);               // (v - mn) * inv
    return fmaf(rintf(tq), p.y, p.x);            // inv==0 -> mn == v (degenerate chunk)
}

__global__ void __launch_bounds__(256) k_quant(const float4* __restrict__ x,
                                               float4* __restrict__ o, int n4) {
    __shared__ unsigned char lut[QLN];           // 8 KB
    __shared__ float4 sq[16];
    __shared__ float  scut[16];
    {
        const uint4* src = (const uint4*)g_qlut;
        uint4* dst = (uint4*)lut;
        for (int i = threadIdx.x; i < (int)(QLN / 16); i += 256) dst[i] = src[i];
    }
    if (threadIdx.x < 16) { sq[threadIdx.x] = g_q[threadIdx.x]; scut[threadIdx.x] = g_cutv[threadIdx.x]; }
    __syncthreads();
    int T = gridDim.x * blockDim.x;
    int g = blockIdx.x * blockDim.x + threadIdx.x;
    for (int i = g; i < n4; i += 2 * T) {
        float4 a = __ldcs(&x[i]);
        bool hb = (i + T) < n4;
        float4 b = hb ? __ldcs(&x[i + T]) : a;
        float4 ra, rb;
        ra.x = qone(a.x, lut, sq, scut);
        ra.y = qone(a.y, lut, sq, scut);
        ra.z = qone(a.z, lut, sq, scut);
        ra.w = qone(a.w, lut, sq, scut);
        rb.x = qone(b.x, lut, sq, scut);
        rb.y = qone(b.y, lut, sq, scut);
        rb.z = qone(b.z, lut, sq, scut);
        rb.w = qone(b.w, lut, sq, scut);
        __stcs(&o[i], ra);
        if (hb) __stcs(&o[i + T], rb);
    }
}

// ---------------- launcher ----------------
extern "C" void kernel_launch(void* const* d_in, const int* in_sizes, int n_in,
                              void* d_out, int out_size) {
    const float4* x = (const float4*)d_in[0];
    float4* out = (float4*)d_out;
    int n = in_sizes[0];
    int n4 = n / 4;

    cudaFuncSetAttribute(k_hist1, cudaFuncAttributeMaxDynamicSharedMemorySize, 131072);
    cudaFuncSetAttribute(k_hist2, cudaFuncAttributeMaxDynamicSharedMemorySize, 65536);

    k_hist1  <<< NPART, 1024, 131072 >>> (x, n4);   // raw 16-bit coarse histogram (packed u16)
    k_reduce <<< (HB / 2) / 1024, 1024 >>> ();      // sum packed partials -> mono-ordered g_hist16
    k_scan1  <<< 1, 1024 >>> ((unsigned)n);         // locate cut bins, slots, raw slot LUT
    k_hist2  <<< 444, 512, 65536 >>> (x, n4);       // fine histogram (mono low 16), L2-resident
    k_scan2a <<< MAX_SLOTS * NSEG, 256 >>> ();      // per-segment partial sums
    k_scan2b <<< 32, 128 >>> ();                    // exact order statistics
    k_zero2  <<< 128, 256 >>> ();                   // re-zero used fine-hist slots
    k_params <<< 1, 32 >>> ();                      // mn/step/inv/mn*inv + cuts
    k_blut   <<< QLN / 1024, 1024 >>> ();           // raw 13-bit bin -> chunk LUT
    k_quant  <<< 1184, 256 >>> (x, out, n4);        // lean elementwise quantize
}

// round 13
// speedup vs baseline: 1.2192x; 1.1877x over previous
#include <cuda_runtime.h>
#include <cstdint>

// ---------------- configuration ----------------
#define HB_BITS   16
#define HB        (1u << HB_BITS)     // 65536 coarse bins (top 16 raw bits)
#define LOWB      16
#define LOWN      (1u << LOWB)        // 65536 fine bins (low 16 mono bits)
#define NPART     148                 // one coarse-hist block per SM
#define MAX_SLOTS 32
#define NSEG      16
#define SEG_BINS  (LOWN / NSEG)       // 4096 bins per scan segment
#define QL_BITS   13
#define QLN       (1u << QL_BITS)     // 8192-entry quant LUT (top 13 raw bits)

// ---------------- static scratch ----------------
__device__ __align__(16) unsigned g_part1[(size_t)NPART * (HB / 2)];   // 19.4 MB packed u16, overwritten each run
__device__ __align__(16) unsigned g_hist16[HB];                        // mono-indexed, overwritten by k_reduce
__device__ __align__(16) unsigned g_hist2[(size_t)MAX_SLOTS * LOWN];   // 8 MB, zeroed by k_zero2
__device__ __align__(16) unsigned g_part2[MAX_SLOTS][NSEG];
__device__ __align__(16) unsigned char g_lut16[HB];                    // RAW coarse bin -> slot+1 (rebuilt each run)
__device__ __align__(16) unsigned char g_qlut[QLN];                    // RAW 13-bit bin -> base | amb<<4 (rebuilt)
__device__ int      g_tbin[32];       // mono coarse bins of targets
__device__ unsigned g_trr[32];
__device__ int      g_tslot[32];
__device__ int      g_nslots;
__device__ float    g_tval[32];
__device__ float    g_cutv[16];
__device__ float4   g_q[16];          // x=mn, y=step, z=inv

// order-preserving maps
__device__ __forceinline__ unsigned mono_bits(unsigned b) {
    return b ^ ((unsigned)(((int)b) >> 31) | 0x80000000u);
}
__device__ __forceinline__ unsigned mono_key(float f) { return mono_bits(__float_as_uint(f)); }
__device__ __forceinline__ float unmono_key(unsigned k) {
    unsigned b = (k & 0x80000000u) ? (k & 0x7FFFFFFFu) : ~k;
    return __uint_as_float(b);
}
// 16-bit bin permutations between raw-bit order and mono (value) order
__device__ __forceinline__ unsigned raw2mono16(unsigned r) { return (r & 0x8000u) ? (r ^ 0xFFFFu) : (r ^ 0x8000u); }
__device__ __forceinline__ unsigned mono2raw16(unsigned m) { return (m & 0x8000u) ? (m ^ 0x8000u) : (m ^ 0xFFFFu); }

// ---------------- pass 1: raw 16-bit coarse histogram, packed u16 counters ----------------
__device__ __forceinline__ void h1_acc(unsigned* sh, float4 a) {
    unsigned k0 = __float_as_uint(a.x) >> 16, k1 = __float_as_uint(a.y) >> 16;
    unsigned k2 = __float_as_uint(a.z) >> 16, k3 = __float_as_uint(a.w) >> 16;
    atomicAdd(&sh[k0 >> 1], 1u << ((k0 & 1u) << 4));
    atomicAdd(&sh[k1 >> 1], 1u << ((k1 & 1u) << 4));
    atomicAdd(&sh[k2 >> 1], 1u << ((k2 & 1u) << 4));
    atomicAdd(&sh[k3 >> 1], 1u << ((k3 & 1u) << 4));
}

__global__ void __launch_bounds__(1024) k_hist1(const float4* __restrict__ x, int n4) {
    extern __shared__ unsigned sh[];              // HB/2 = 32768 words (128 KB)
    for (int i = threadIdx.x; i < (int)(HB / 2); i += 1024) sh[i] = 0u;
    __syncthreads();
    int T = gridDim.x * blockDim.x;
    int g = blockIdx.x * blockDim.x + threadIdx.x;
    for (int i = g; i < n4; i += 4 * T) {
        float4 a0 = __ldcs(&x[i]);
        bool h1 = (i + T) < n4, h2 = (i + 2 * T) < n4, h3 = (i + 3 * T) < n4;
        float4 a1, a2, a3;
        if (h1) a1 = __ldcs(&x[i + T]);
        if (h2) a2 = __ldcs(&x[i + 2 * T]);
        if (h3) a3 = __ldcs(&x[i + 3 * T]);
        h1_acc(sh, a0);
        if (h1) h1_acc(sh, a1);
        if (h2) h1_acc(sh, a2);
        if (h3) h1_acc(sh, a3);
    }
    __syncthreads();
    unsigned* dst = g_part1 + (size_t)blockIdx.x * (HB / 2);
    for (int i = threadIdx.x; i < (int)(HB / 2); i += 1024) dst[i] = sh[i];   // packed
}

// ---------------- reduce packed partials -> mono-ordered g_hist16 ----------------
__global__ void __launch_bounds__(1024) k_reduce() {
    unsigned w = blockIdx.x * 1024u + threadIdx.x;     // packed word index (raw bins 2w, 2w+1)
    unsigned lo = 0, hi = 0;
#pragma unroll 8
    for (int k = 0; k < NPART; k++) {
        unsigned v = g_part1[(size_t)k * (HB / 2) + w];
        lo += v & 0xFFFFu;
        hi += v >> 16;
    }
    g_hist16[raw2mono16(2u * w)]      = lo;
    g_hist16[raw2mono16(2u * w + 1u)] = hi;
}

// ---------------- scan coarse histogram (mono order), locate target bins ----------------
__global__ void __launch_bounds__(1024) k_scan1(unsigned n) {
    __shared__ unsigned pre[1024];
    __shared__ unsigned wsum[32];
    __shared__ int      sbin[32];
    __shared__ unsigned srr[32];
    __shared__ int      sslot[32];

    int t = threadIdx.x, lane = t & 31, w = t >> 5;
    unsigned s = 0;
    for (int k = 0; k < 64; k++) s += g_hist16[t * 64 + k];  // group sum (64 mono bins/thread)

    unsigned inc = s;
#pragma unroll
    for (int o = 1; o < 32; o <<= 1) {
        unsigned u = __shfl_up_sync(0xFFFFFFFFu, inc, o);
        if (lane >= o) inc += u;
    }
    if (lane == 31) wsum[w] = inc;
    __syncthreads();
    if (t < 32) {
        unsigned v = wsum[t], ss = v;
#pragma unroll
        for (int o = 1; o < 32; o <<= 1) {
            unsigned u = __shfl_up_sync(0xFFFFFFFFu, ss, o);
            if (t >= o) ss += u;
        }
        wsum[t] = ss - v;
    }
    __syncthreads();
    pre[t] = inc + wsum[w];          // inclusive prefix of 1024 group sums
    __syncthreads();

    if (t < 32) {
        unsigned S = n >> 4;
        unsigned r;
        if (t == 0)       r = 0u;
        else if (t == 31) r = n - 1u;
        else {
            unsigned c = (unsigned)(t + 1) >> 1;
            r = c * S - ((t & 1) ? 1u : 0u);
        }
        int lo = 0, hi = 1023;
        while (lo < hi) { int mid = (lo + hi) >> 1; if (pre[mid] > r) hi = mid; else lo = mid + 1; }
        unsigned run = lo ? pre[lo - 1] : 0u;
        int bin = -1;
        for (int k = 0; k < 64; k++) {
            unsigned c = g_hist16[lo * 64 + k];
            if (r < run + c) { bin = lo * 64 + k; srr[t] = r - run; break; }
            run += c;
        }
        sbin[t] = bin;
    }
    __syncthreads();

    for (int i = t; i < (int)HB; i += 1024) g_lut16[i] = 0;  // zero slot LUT (raw-indexed)
    if (t == 0) {
        int ns = 0;
        for (int i = 0; i < 32; i++) {
            int sl = -1;
            for (int j = 0; j < i; j++) if (sbin[j] == sbin[i]) { sl = sslot[j]; break; }
            if (sl < 0) sl = ns++;
            sslot[i] = sl;
        }
        g_nslots = ns;
    }
    __syncthreads();
    if (t == 0)
        for (int i = 0; i < 32; i++)
            g_lut16[mono2raw16((unsigned)sbin[i])] = (unsigned char)(sslot[i] + 1);
    if (t < 32) { g_tbin[t] = sbin[t]; g_trr[t] = srr[t]; g_tslot[t] = sslot[t]; }
}

// ---------------- pass 2: fine histogram (low 16 mono bits) for cut bins ----------------
__device__ __forceinline__ void h2_acc(const unsigned char* lut, float4 a) {
    float vv[4] = { a.x, a.y, a.z, a.w };
#pragma unroll
    for (int j = 0; j < 4; j++) {
        unsigned char sl = lut[__float_as_uint(vv[j]) >> 16];
        if (sl) {
            unsigned m = mono_key(vv[j]);
            atomicAdd(&g_hist2[(size_t)(sl - 1) * LOWN + (m & 0xFFFFu)], 1u);
        }
    }
}

__global__ void __launch_bounds__(512) k_hist2(const float4* __restrict__ x, int n4) {
    extern __shared__ unsigned char lut[];   // 64 KB, raw-indexed
    {
        const uint4* src = (const uint4*)g_lut16;
        uint4* dst = (uint4*)lut;
        for (int i = threadIdx.x; i < (int)(HB / 16); i += 512) dst[i] = src[i];
    }
    __syncthreads();
    int T = gridDim.x * blockDim.x;
    int g = blockIdx.x * blockDim.x + threadIdx.x;
    for (int i = g; i < n4; i += 4 * T) {
        float4 a0 = __ldcs(&x[i]);
        bool h1 = (i + T) < n4, h2 = (i + 2 * T) < n4, h3 = (i + 3 * T) < n4;
        float4 a1, a2, a3;
        if (h1) a1 = __ldcs(&x[i + T]);
        if (h2) a2 = __ldcs(&x[i + 2 * T]);
        if (h3) a3 = __ldcs(&x[i + 3 * T]);
        h2_acc(lut, a0);
        if (h1) h2_acc(lut, a1);
        if (h2) h2_acc(lut, a2);
        if (h3) h2_acc(lut, a3);
    }
}

// ---------------- scan2a: per-segment partial sums ----------------
__global__ void __launch_bounds__(256) k_scan2a() {
    int slot = blockIdx.x / NSEG;
    if (slot >= g_nslots) return;
    int seg = blockIdx.x % NSEG;
    const uint4* h = (const uint4*)(g_hist2 + (size_t)slot * LOWN + (size_t)seg * SEG_BINS);
    int t = threadIdx.x;
    unsigned s = 0;
#pragma unroll
    for (int i = 0; i < 4; i++) {               // 16 bins per thread
        uint4 u = h[t * 4 + i];
        s += u.x + u.y + u.z + u.w;
    }
#pragma unroll
    for (int o = 16; o; o >>= 1) s += __shfl_down_sync(0xFFFFFFFFu, s, o);
    __shared__ unsigned ws[8];
    if ((t & 31) == 0) ws[t >> 5] = s;
    __syncthreads();
    if (t < 8) {
        unsigned v = ws[t];
#pragma unroll
        for (int o = 4; o; o >>= 1) v += __shfl_down_sync(0xFFu, v, o, 8);
        if (t == 0) g_part2[slot][seg] = v;
    }
}

// ---------------- scan2b: exact order statistic per target ----------------
__global__ void __launch_bounds__(128) k_scan2b() {
    int t = blockIdx.x;
    int slot = g_tslot[t];
    unsigned rr = g_trr[t];
    unsigned bin = (unsigned)g_tbin[t];
    int tid = threadIdx.x;

    __shared__ int s_seg;
    __shared__ unsigned s_rr2;
    __shared__ unsigned s[128];

    if (tid == 0) {
        unsigned run = 0; int seg = -1;
        for (int k = 0; k < NSEG; k++) {
            unsigned c = g_part2[slot][k];
            if (seg < 0 && rr < run + c) { seg = k; s_rr2 = rr - run; }
            run += c;
        }
        s_seg = seg;
    }
    __syncthreads();
    int seg = s_seg;
    unsigned rr2 = s_rr2;

    const uint4* h = (const uint4*)(g_hist2 + (size_t)slot * LOWN + (size_t)seg * SEG_BINS);
    uint4 u[8];
    unsigned sum = 0;
#pragma unroll
    for (int i = 0; i < 8; i++) {               // 32 bins per thread
        u[i] = h[tid * 8 + i];
        sum += u[i].x + u[i].y + u[i].z + u[i].w;
    }
    s[tid] = sum; __syncthreads();
    for (int o = 1; o < 128; o <<= 1) {
        unsigned v = (tid >= o) ? s[tid - o] : 0u;
        __syncthreads();
        s[tid] += v;
        __syncthreads();
    }
    unsigned incl2 = s[tid], excl2 = incl2 - sum;
    if (rr2 >= excl2 && rr2 < incl2) {
        unsigned run = excl2, low = 0;
        bool found = false;
        for (int i = 0; i < 8 && !found; i++) {
            unsigned vv[4] = { u[i].x, u[i].y, u[i].z, u[i].w };
            for (int j = 0; j < 4; j++) {
                if (!found) {
                    if (rr2 < run + vv[j]) { low = (unsigned)(tid * 32 + i * 4 + j); found = true; }
                    else run += vv[j];
                }
            }
        }
        unsigned key = (bin << LOWB) | ((unsigned)seg * SEG_BINS + low);
        g_tval[t] = unmono_key(key);
    }
}

// ---------------- zero used fine-hist slots for replay ----------------
__global__ void __launch_bounds__(256) k_zero2() {
    unsigned total4 = (unsigned)g_nslots * (LOWN / 4u);
    uint4* p = (uint4*)g_hist2;
    uint4 z = make_uint4(0u, 0u, 0u, 0u);
    unsigned stride = gridDim.x * blockDim.x;
    for (unsigned i = blockIdx.x * blockDim.x + threadIdx.x; i < total4; i += stride) p[i] = z;
}

// ---------------- per-chunk params ----------------
__global__ void k_params() {
    int c = threadIdx.x;
    if (c < 16) {
        float mn = (c == 0)  ? g_tval[0]  : g_tval[2 * c];
        float mx = (c == 15) ? g_tval[31] : g_tval[2 * c + 1];
        float step = __fdiv_rn(__fsub_rn(mx, mn), 15.0f);
        float inv  = (step == 0.0f) ? 0.0f : __fdiv_rn(1.0f, step);
        g_q[c] = make_float4(mn, step, inv, 0.0f);
        g_cutv[c] = (c == 0) ? __int_as_float(0xFF800000) : mn;
    }
}

// ---------------- build 13-bit RAW-bin quant LUT: base chunk | #ambiguous<<4 ----------------
__global__ void __launch_bounds__(1024) k_blut() {
    __shared__ unsigned kc[16];
    if (threadIdx.x >= 1 && threadIdx.x < 16) kc[threadIdx.x] = mono_key(g_cutv[threadIdx.x]);
    __syncthreads();
    unsigned r = blockIdx.x * 1024u + threadIdx.x;
    unsigned m0 = mono_bits(r << (32 - QL_BITS));
    unsigned m1 = mono_bits((r << (32 - QL_BITS)) | ((1u << (32 - QL_BITS)) - 1u));
    unsigned mlo = min(m0, m1), mhi = max(m0, m1);
    int base = 0, amb = 0;
#pragma unroll
    for (int j = 1; j < 16; j++) {
        unsigned k = kc[j];
        base += (k <= mlo);
        amb  += (k > mlo && k <= mhi);
    }
    g_qlut[r] = (unsigned char)(base | (amb << 4));
}

// ---------------- final quantize pass ----------------
__device__ __forceinline__ float qone(float v, const unsigned char* lut,
                                      float mn_r, float st_r, float iv_r,
                                      const float* scut) {
    unsigned e = lut[__float_as_uint(v) >> (32 - QL_BITS)];
    int c = e & 15;
    int amb = e >> 4;
    if (amb) {                                   // rare: cut(s) inside this bin (~3% of elems)
        int b = c;
#pragma unroll 1
        for (int t = 1; t <= amb; t++) c += (v >= scut[b + t]) ? 1 : 0;
    }
    float mn = __shfl_sync(0xFFFFFFFFu, mn_r, c);   // conflict-free param fetch
    float st = __shfl_sync(0xFFFFFFFFu, st_r, c);
    float iv = __shfl_sync(0xFFFFFFFFu, iv_r, c);
    return fmaf(rintf((v - mn) * iv), st, mn);      // iv==0 -> v==mn (degenerate chunk)
}

__global__ void __launch_bounds__(256) k_quant(const float4* __restrict__ x,
                                               float4* __restrict__ o, int n4) {
    __shared__ unsigned char lut[QLN];           // 8 KB
    __shared__ float  scut[16];
    {
        const uint4* src = (const uint4*)g_qlut;
        uint4* dst = (uint4*)lut;
        for (int i = threadIdx.x; i < (int)(QLN / 16); i += 256) dst[i] = src[i];
    }
    int lane = threadIdx.x & 31;
    float mn_r = 0.f, st_r = 0.f, iv_r = 0.f;
    if (lane < 16) {
        float4 q = g_q[lane];
        mn_r = q.x; st_r = q.y; iv_r = q.z;
    }
    if (threadIdx.x < 16) scut[threadIdx.x] = g_cutv[threadIdx.x];
    __syncthreads();
    int T = gridDim.x * blockDim.x;
    int g = blockIdx.x * blockDim.x + threadIdx.x;
    for (int i = g; i < n4; i += 2 * T) {        // warp-uniform bounds (n4, T multiples of 32)
        float4 a = __ldcs(&x[i]);
        bool hb = (i + T) < n4;
        float4 b;
        if (hb) b = __ldcs(&x[i + T]);
        float4 ra;
        ra.x = qone(a.x, lut, mn_r, st_r, iv_r, scut);
        ra.y = qone(a.y, lut, mn_r, st_r, iv_r, scut);
        ra.z = qone(a.z, lut, mn_r, st_r, iv_r, scut);
        ra.w = qone(a.w, lut, mn_r, st_r, iv_r, scut);
        __stcs(&o[i], ra);
        if (hb) {
            float4 rb;
            rb.x = qone(b.x, lut, mn_r, st_r, iv_r, scut);
            rb.y = qone(b.y, lut, mn_r, st_r, iv_r, scut);
            rb.z = qone(b.z, lut, mn_r, st_r, iv_r, scut);
            rb.w = qone(b.w, lut, mn_r, st_r, iv_r, scut);
            __stcs(&o[i + T], rb);
        }
    }
}

// ---------------- launcher ----------------
extern "C" void kernel_launch(void* const* d_in, const int* in_sizes, int n_in,
                              void* d_out, int out_size) {
    const float4* x = (const float4*)d_in[0];
    float4* out = (float4*)d_out;
    int n = in_sizes[0];
    int n4 = n / 4;

    cudaFuncSetAttribute(k_hist1, cudaFuncAttributeMaxDynamicSharedMemorySize, 131072);
    cudaFuncSetAttribute(k_hist2, cudaFuncAttributeMaxDynamicSharedMemorySize, 65536);

    k_hist1  <<< NPART, 1024, 131072 >>> (x, n4);   // raw 16-bit coarse histogram (packed u16)
    k_reduce <<< (HB / 2) / 1024, 1024 >>> ();      // sum packed partials -> mono-ordered g_hist16
    k_scan1  <<< 1, 1024 >>> ((unsigned)n);         // locate cut bins, slots, raw slot LUT
    k_hist2  <<< 888, 512, 65536 >>> (x, n4);       // fine histogram (mono low 16), 4-wide MLP
    k_scan2a <<< MAX_SLOTS * NSEG, 256 >>> ();      // per-segment partial sums
    k_scan2b <<< 32, 128 >>> ();                    // exact order statistics
    k_zero2  <<< 128, 256 >>> ();                   // re-zero used fine-hist slots
    k_params <<< 1, 32 >>> ();                      // mn/step/inv + cuts
    k_blut   <<< QLN / 1024, 1024 >>> ();           // raw 13-bit bin -> chunk LUT
    k_quant  <<< 1184, 256 >>> (x, out, n4);        // quantize: byte-LUT + shuffle params
}

// round 14
// speedup vs baseline: 1.2291x; 1.0082x over previous
#include <cuda_runtime.h>
#include <cstdint>

// ---------------- configuration ----------------
#define HB_BITS   16
#define HB        (1u << HB_BITS)     // 65536 coarse bins (top 16 raw bits)
#define LOWB      16
#define LOWN      (1u << LOWB)        // 65536 fine bins (low 16 mono bits)
#define NPART     148                 // one coarse-hist block per SM
#define MAX_SLOTS 32
#define NSEG      16
#define SEG_BINS  (LOWN / NSEG)       // 4096 bins per scan segment
#define QL_BITS   14
#define QLN       (1u << QL_BITS)     // 16384-entry quant LUT (top 14 raw bits)

// ---------------- static scratch ----------------
__device__ __align__(16) unsigned g_part1[(size_t)NPART * (HB / 2)];   // 19.4 MB packed u16, overwritten each run
__device__ __align__(16) unsigned g_hist16[HB];                        // mono-indexed, overwritten by k_reduce
__device__ __align__(16) unsigned g_hist2[(size_t)MAX_SLOTS * LOWN];   // 8 MB, zeroed by k_zero2
__device__ __align__(16) unsigned g_part2[MAX_SLOTS][NSEG];
__device__ __align__(16) unsigned char g_lut16[HB];                    // RAW coarse bin -> slot+1 (rebuilt each run)
__device__ __align__(16) unsigned char g_qlut[QLN];                    // RAW 14-bit bin -> base | amb<<4 (rebuilt)
__device__ int      g_tbin[32];       // mono coarse bins of targets
__device__ unsigned g_trr[32];
__device__ int      g_tslot[32];
__device__ int      g_nslots;
__device__ float    g_tval[32];
__device__ float    g_cutv[16];
__device__ float4   g_q[16];          // x=1/step (A), y=-mn/step (B), z=step (C), w=mn (D)

// order-preserving maps
__device__ __forceinline__ unsigned mono_bits(unsigned b) {
    return b ^ ((unsigned)(((int)b) >> 31) | 0x80000000u);
}
__device__ __forceinline__ unsigned mono_key(float f) { return mono_bits(__float_as_uint(f)); }
__device__ __forceinline__ float unmono_key(unsigned k) {
    unsigned b = (k & 0x80000000u) ? (k & 0x7FFFFFFFu) : ~k;
    return __uint_as_float(b);
}
// 16-bit bin permutations between raw-bit order and mono (value) order
__device__ __forceinline__ unsigned raw2mono16(unsigned r) { return (r & 0x8000u) ? (r ^ 0xFFFFu) : (r ^ 0x8000u); }
__device__ __forceinline__ unsigned mono2raw16(unsigned m) { return (m & 0x8000u) ? (m ^ 0x8000u) : (m ^ 0xFFFFu); }

// ---------------- pass 1: raw 16-bit coarse histogram, packed u16 counters ----------------
__device__ __forceinline__ void h1_acc(unsigned sbase, float4 a) {
    unsigned k0 = __float_as_uint(a.x) >> 16, k1 = __float_as_uint(a.y) >> 16;
    unsigned k2 = __float_as_uint(a.z) >> 16, k3 = __float_as_uint(a.w) >> 16;
    asm volatile("red.shared.add.u32 [%0], %1;" :: "r"(sbase + (k0 >> 1) * 4u), "r"(1u << ((k0 & 1u) << 4)));
    asm volatile("red.shared.add.u32 [%0], %1;" :: "r"(sbase + (k1 >> 1) * 4u), "r"(1u << ((k1 & 1u) << 4)));
    asm volatile("red.shared.add.u32 [%0], %1;" :: "r"(sbase + (k2 >> 1) * 4u), "r"(1u << ((k2 & 1u) << 4)));
    asm volatile("red.shared.add.u32 [%0], %1;" :: "r"(sbase + (k3 >> 1) * 4u), "r"(1u << ((k3 & 1u) << 4)));
}

__global__ void __launch_bounds__(1024) k_hist1(const float4* __restrict__ x, int n4) {
    extern __shared__ unsigned sh[];              // HB/2 = 32768 words (128 KB)
    for (int i = threadIdx.x; i < (int)(HB / 2); i += 1024) sh[i] = 0u;
    __syncthreads();
    unsigned sbase = (unsigned)__cvta_generic_to_shared(sh);
    int T = gridDim.x * blockDim.x;
    int g = blockIdx.x * blockDim.x + threadIdx.x;
    for (int i = g; i < n4; i += 4 * T) {
        float4 a0 = __ldcs(&x[i]);
        bool h1 = (i + T) < n4, h2 = (i + 2 * T) < n4, h3 = (i + 3 * T) < n4;
        float4 a1, a2, a3;
        if (h1) a1 = __ldcs(&x[i + T]);
        if (h2) a2 = __ldcs(&x[i + 2 * T]);
        if (h3) a3 = __ldcs(&x[i + 3 * T]);
        h1_acc(sbase, a0);
        if (h1) h1_acc(sbase, a1);
        if (h2) h1_acc(sbase, a2);
        if (h3) h1_acc(sbase, a3);
    }
    __syncthreads();
    unsigned* dst = g_part1 + (size_t)blockIdx.x * (HB / 2);
    for (int i = threadIdx.x; i < (int)(HB / 2); i += 1024) dst[i] = sh[i];   // packed
}

// ---------------- reduce packed partials -> mono-ordered g_hist16 ----------------
__global__ void __launch_bounds__(1024) k_reduce() {
    unsigned w = blockIdx.x * 1024u + threadIdx.x;     // packed word index (raw bins 2w, 2w+1)
    unsigned lo = 0, hi = 0;
#pragma unroll 8
    for (int k = 0; k < NPART; k++) {
        unsigned v = g_part1[(size_t)k * (HB / 2) + w];
        lo += v & 0xFFFFu;
        hi += v >> 16;
    }
    g_hist16[raw2mono16(2u * w)]      = lo;
    g_hist16[raw2mono16(2u * w + 1u)] = hi;
}

// ---------------- scan coarse histogram (mono order), locate target bins ----------------
__global__ void __launch_bounds__(1024) k_scan1(unsigned n) {
    __shared__ unsigned pre[1024];
    __shared__ unsigned wsum[32];
    __shared__ int      sbin[32];
    __shared__ unsigned srr[32];
    __shared__ int      sslot[32];

    int t = threadIdx.x, lane = t & 31, w = t >> 5;
    unsigned s = 0;
    for (int k = 0; k < 64; k++) s += g_hist16[t * 64 + k];  // group sum (64 mono bins/thread)

    unsigned inc = s;
#pragma unroll
    for (int o = 1; o < 32; o <<= 1) {
        unsigned u = __shfl_up_sync(0xFFFFFFFFu, inc, o);
        if (lane >= o) inc += u;
    }
    if (lane == 31) wsum[w] = inc;
    __syncthreads();
    if (t < 32) {
        unsigned v = wsum[t], ss = v;
#pragma unroll
        for (int o = 1; o < 32; o <<= 1) {
            unsigned u = __shfl_up_sync(0xFFFFFFFFu, ss, o);
            if (t >= o) ss += u;
        }
        wsum[t] = ss - v;
    }
    __syncthreads();
    pre[t] = inc + wsum[w];          // inclusive prefix of 1024 group sums
    __syncthreads();

    if (t < 32) {
        unsigned S = n >> 4;
        unsigned r;
        if (t == 0)       r = 0u;
        else if (t == 31) r = n - 1u;
        else {
            unsigned c = (unsigned)(t + 1) >> 1;
            r = c * S - ((t & 1) ? 1u : 0u);
        }
        int lo = 0, hi = 1023;
        while (lo < hi) { int mid = (lo + hi) >> 1; if (pre[mid] > r) hi = mid; else lo = mid + 1; }
        unsigned run = lo ? pre[lo - 1] : 0u;
        int bin = -1;
        for (int k = 0; k < 64; k++) {
            unsigned c = g_hist16[lo * 64 + k];
            if (r < run + c) { bin = lo * 64 + k; srr[t] = r - run; break; }
            run += c;
        }
        sbin[t] = bin;
    }
    __syncthreads();

    for (int i = t; i < (int)HB; i += 1024) g_lut16[i] = 0;  // zero slot LUT (raw-indexed)
    if (t == 0) {
        int ns = 0;
        for (int i = 0; i < 32; i++) {
            int sl = -1;
            for (int j = 0; j < i; j++) if (sbin[j] == sbin[i]) { sl = sslot[j]; break; }
            if (sl < 0) sl = ns++;
            sslot[i] = sl;
        }
        g_nslots = ns;
    }
    __syncthreads();
    if (t == 0)
        for (int i = 0; i < 32; i++)
            g_lut16[mono2raw16((unsigned)sbin[i])] = (unsigned char)(sslot[i] + 1);
    if (t < 32) { g_tbin[t] = sbin[t]; g_trr[t] = srr[t]; g_tslot[t] = sslot[t]; }
}

// ---------------- pass 2: fine histogram (low 16 mono bits) for cut bins ----------------
// Branch-free: predicated red.global.add (no BSSY/BSYNC, no return scoreboard).
__device__ __forceinline__ void h2_acc(const unsigned char* lut, float4 a) {
    float vv[4] = { a.x, a.y, a.z, a.w };
#pragma unroll
    for (int j = 0; j < 4; j++) {
        unsigned sl = lut[__float_as_uint(vv[j]) >> 16];
        unsigned m = mono_key(vv[j]) & 0xFFFFu;
        unsigned* ptr = g_hist2 + (size_t)((sl - 1u) & 31u) * LOWN + m;   // masked: always in-bounds
        asm volatile("{\n\t"
                     ".reg .pred p;\n\t"
                     "setp.ne.u32 p, %0, 0;\n\t"
                     "@p red.global.add.u32 [%1], %2;\n\t"
                     "}" :: "r"(sl), "l"(ptr), "r"(1u) : "memory");
    }
}

__global__ void __launch_bounds__(512) k_hist2(const float4* __restrict__ x, int n4) {
    extern __shared__ unsigned char lut[];   // 64 KB, raw-indexed
    {
        const uint4* src = (const uint4*)g_lut16;
        uint4* dst = (uint4*)lut;
        for (int i = threadIdx.x; i < (int)(HB / 16); i += 512) dst[i] = src[i];
    }
    __syncthreads();
    int T = gridDim.x * blockDim.x;
    int g = blockIdx.x * blockDim.x + threadIdx.x;
    for (int i = g; i < n4; i += 4 * T) {
        float4 a0 = __ldcs(&x[i]);
        bool h1 = (i + T) < n4, h2 = (i + 2 * T) < n4, h3 = (i + 3 * T) < n4;
        float4 a1, a2, a3;
        if (h1) a1 = __ldcs(&x[i + T]);
        if (h2) a2 = __ldcs(&x[i + 2 * T]);
        if (h3) a3 = __ldcs(&x[i + 3 * T]);
        h2_acc(lut, a0);
        if (h1) h2_acc(lut, a1);
        if (h2) h2_acc(lut, a2);
        if (h3) h2_acc(lut, a3);
    }
}

// ---------------- scan2a: per-segment partial sums ----------------
__global__ void __launch_bounds__(256) k_scan2a() {
    int slot = blockIdx.x / NSEG;
    if (slot >= g_nslots) return;
    int seg = blockIdx.x % NSEG;
    const uint4* h = (const uint4*)(g_hist2 + (size_t)slot * LOWN + (size_t)seg * SEG_BINS);
    int t = threadIdx.x;
    unsigned s = 0;
#pragma unroll
    for (int i = 0; i < 4; i++) {               // 16 bins per thread
        uint4 u = h[t * 4 + i];
        s += u.x + u.y + u.z + u.w;
    }
#pragma unroll
    for (int o = 16; o; o >>= 1) s += __shfl_down_sync(0xFFFFFFFFu, s, o);
    __shared__ unsigned ws[8];
    if ((t & 31) == 0) ws[t >> 5] = s;
    __syncthreads();
    if (t < 8) {
        unsigned v = ws[t];
#pragma unroll
        for (int o = 4; o; o >>= 1) v += __shfl_down_sync(0xFFu, v, o, 8);
        if (t == 0) g_part2[slot][seg] = v;
    }
}

// ---------------- scan2b: exact order statistic per target ----------------
__global__ void __launch_bounds__(128) k_scan2b() {
    int t = blockIdx.x;
    int slot = g_tslot[t];
    unsigned rr = g_trr[t];
    unsigned bin = (unsigned)g_tbin[t];
    int tid = threadIdx.x;

    __shared__ int s_seg;
    __shared__ unsigned s_rr2;
    __shared__ unsigned s[128];

    if (tid == 0) {
        unsigned run = 0; int seg = -1;
        for (int k = 0; k < NSEG; k++) {
            unsigned c = g_part2[slot][k];
            if (seg < 0 && rr < run + c) { seg = k; s_rr2 = rr - run; }
            run += c;
        }
        s_seg = seg;
    }
    __syncthreads();
    int seg = s_seg;
    unsigned rr2 = s_rr2;

    const uint4* h = (const uint4*)(g_hist2 + (size_t)slot * LOWN + (size_t)seg * SEG_BINS);
    uint4 u[8];
    unsigned sum = 0;
#pragma unroll
    for (int i = 0; i < 8; i++) {               // 32 bins per thread
        u[i] = h[tid * 8 + i];
        sum += u[i].x + u[i].y + u[i].z + u[i].w;
    }
    s[tid] = sum; __syncthreads();
    for (int o = 1; o < 128; o <<= 1) {
        unsigned v = (tid >= o) ? s[tid - o] : 0u;
        __syncthreads();
        s[tid] += v;
        __syncthreads();
    }
    unsigned incl2 = s[tid], excl2 = incl2 - sum;
    if (rr2 >= excl2 && rr2 < incl2) {
        unsigned run = excl2, low = 0;
        bool found = false;
        for (int i = 0; i < 8 && !found; i++) {
            unsigned vv[4] = { u[i].x, u[i].y, u[i].z, u[i].w };
            for (int j = 0; j < 4; j++) {
                if (!found) {
                    if (rr2 < run + vv[j]) { low = (unsigned)(tid * 32 + i * 4 + j); found = true; }
                    else run += vv[j];
                }
            }
        }
        unsigned key = (bin << LOWB) | ((unsigned)seg * SEG_BINS + low);
        g_tval[t] = unmono_key(key);
    }
}

// ---------------- zero used fine-hist slots for replay ----------------
__global__ void __launch_bounds__(256) k_zero2() {
    unsigned total4 = (unsigned)g_nslots * (LOWN / 4u);
    uint4* p = (uint4*)g_hist2;
    uint4 z = make_uint4(0u, 0u, 0u, 0u);
    unsigned stride = gridDim.x * blockDim.x;
    for (unsigned i = blockIdx.x * blockDim.x + threadIdx.x; i < total4; i += stride) p[i] = z;
}

// ---------------- per-chunk params: {A=1/step, B=-mn/step, C=step, D=mn} ----------------
__global__ void k_params() {
    int c = threadIdx.x;
    if (c < 16) {
        float mn = (c == 0)  ? g_tval[0]  : g_tval[2 * c];
        float mx = (c == 15) ? g_tval[31] : g_tval[2 * c + 1];
        float step = __fdiv_rn(__fsub_rn(mx, mn), 15.0f);
        float inv  = (step == 0.0f) ? 0.0f : __fdiv_rn(1.0f, step);
        g_q[c] = make_float4(inv, -mn * inv, step, mn);
        g_cutv[c] = (c == 0) ? __int_as_float(0xFF800000) : mn;
    }
}

// ---------------- build 14-bit RAW-bin quant LUT: base chunk | #ambiguous<<4 ----------------
__global__ void __launch_bounds__(1024) k_blut() {
    __shared__ unsigned kc[16];
    if (threadIdx.x >= 1 && threadIdx.x < 16) kc[threadIdx.x] = mono_key(g_cutv[threadIdx.x]);
    __syncthreads();
    unsigned r = blockIdx.x * 1024u + threadIdx.x;
    unsigned m0 = mono_bits(r << (32 - QL_BITS));
    unsigned m1 = mono_bits((r << (32 - QL_BITS)) | ((1u << (32 - QL_BITS)) - 1u));
    unsigned mlo = min(m0, m1), mhi = max(m0, m1);
    int base = 0, amb = 0;
#pragma unroll
    for (int j = 1; j < 16; j++) {
        unsigned k = kc[j];
        base += (k <= mlo);
        amb  += (k > mlo && k <= mhi);
    }
    g_qlut[r] = (unsigned char)(base | (amb << 4));
}

// ---------------- final quantize pass ----------------
// Params fetched via conflict-free replicated LDS.128: pq[c*8 + (lane&7)],
// so each 8-lane phase touches 8 distinct 16B bank groups.
__device__ __forceinline__ float qone(float v, const unsigned char* lut,
                                      const float4* pq, const float* scut, int rep) {
    unsigned e = lut[__float_as_uint(v) >> (32 - QL_BITS)];
    int b = e & 15;
    int amb = e >> 4;
    int c = b + (int)((amb > 0) & (v >= scut[b + 1]));   // unconditional single fix-up
    if (amb > 1) {                                        // essentially never taken
#pragma unroll 1
        for (int t2 = 2; t2 <= amb; t2++) c += (v >= scut[b + t2]) ? 1 : 0;
    }
    float4 p = pq[c * 8 + rep];                           // {A, B, C, D}
    return fmaf(rintf(fmaf(v, p.x, p.y)), p.z, p.w);      // A==0 -> result D == mn == v
}

__global__ void __launch_bounds__(256) k_quant(const float4* __restrict__ x,
                                               float4* __restrict__ o, int n4) {
    __shared__ unsigned char lut[QLN];           // 16 KB
    __shared__ float4 pq[16 * 8];                // 2 KB replicated params
    __shared__ float  scut[20];
    {
        const uint4* src = (const uint4*)g_qlut;
        uint4* dst = (uint4*)lut;
        for (int i = threadIdx.x; i < (int)(QLN / 16); i += 256) dst[i] = src[i];
    }
    if (threadIdx.x < 128) pq[threadIdx.x] = g_q[threadIdx.x >> 3];
    if (threadIdx.x < 16)  scut[threadIdx.x] = g_cutv[threadIdx.x];
    if (threadIdx.x >= 16 && threadIdx.x < 20) scut[threadIdx.x] = __int_as_float(0x7F800000); // +inf pad
    __syncthreads();
    int rep = threadIdx.x & 7;
    int T = gridDim.x * blockDim.x;
    int g = blockIdx.x * blockDim.x + threadIdx.x;
    for (int i = g; i < n4; i += 2 * T) {        // warp-uniform bounds (n4, T multiples of 32)
        float4 a = __ldcs(&x[i]);
        bool hb = (i + T) < n4;
        float4 b;
        if (hb) b = __ldcs(&x[i + T]);
        float4 ra;
        ra.x = qone(a.x, lut, pq, scut, rep);
        ra.y = qone(a.y, lut, pq, scut, rep);
        ra.z = qone(a.z, lut, pq, scut, rep);
        ra.w = qone(a.w, lut, pq, scut, rep);
        __stcs(&o[i], ra);
        if (hb) {
            float4 rb;
            rb.x = qone(b.x, lut, pq, scut, rep);
            rb.y = qone(b.y, lut, pq, scut, rep);
            rb.z = qone(b.z, lut, pq, scut, rep);
            rb.w = qone(b.w, lut, pq, scut, rep);
            __stcs(&o[i + T], rb);
        }
    }
}

// ---------------- launcher ----------------
extern "C" void kernel_launch(void* const* d_in, const int* in_sizes, int n_in,
                              void* d_out, int out_size) {
    const float4* x = (const float4*)d_in[0];
    float4* out = (float4*)d_out;
    int n = in_sizes[0];
    int n4 = n / 4;

    cudaFuncSetAttribute(k_hist1, cudaFuncAttributeMaxDynamicSharedMemorySize, 131072);
    cudaFuncSetAttribute(k_hist2, cudaFuncAttributeMaxDynamicSharedMemorySize, 65536);

    k_hist1  <<< NPART, 1024, 131072 >>> (x, n4);   // raw 16-bit coarse histogram (packed u16)
    k_reduce <<< (HB / 2) / 1024, 1024 >>> ();      // sum packed partials -> mono-ordered g_hist16
    k_scan1  <<< 1, 1024 >>> ((unsigned)n);         // locate cut bins, slots, raw slot LUT
    k_hist2  <<< 888, 512, 65536 >>> (x, n4);       // fine histogram, predicated REDG, 4-wide MLP
    k_scan2a <<< MAX_SLOTS * NSEG, 256 >>> ();      // per-segment partial sums
    k_scan2b <<< 32, 128 >>> ();                    // exact order statistics
    k_zero2  <<< 128, 256 >>> ();                   // re-zero used fine-hist slots
    k_params <<< 1, 32 >>> ();                      // A/B/C/D per chunk + cuts
    k_blut   <<< QLN / 1024, 1024 >>> ();           // raw 14-bit bin -> chunk LUT
    k_quant  <<< 1184, 256 >>> (x, out, n4);        // quantize: byte-LUT + conflict-free LDS.128
}